// round 1
// baseline (speedup 1.0000x reference)
#include <cuda_runtime.h>
#include <math.h>

// Batched EKF: N=8192 independent segments, T=64 sequential steps each.
// One thread per segment; symmetric 6x6 covariance (21 scalars) in registers.
// F is sparse: F = I except F[0,2]=F[1,3]=F[4,5]=DT, F[2,2]=a, F[3,3]=b, F[5,5]=c.

#define THREADS 64

__device__ float g_partials[512];

__global__ void __launch_bounds__(THREADS) ekf_kernel(
    const float* __restrict__ params,
    const float* __restrict__ cp,
    const float* __restrict__ init_state,
    const float* __restrict__ meas,
    int N, int T)
{
    const float DT   = 1.0f / 120.0f;
    const float GRAV = 9.81f;
    const float KS   = 100.0f;
    const float WRAP = 4.71238898038469f;    // 1.5*pi
    const float TWOPI = 6.283185307179586f;

    int n = blockIdx.x * THREADS + threadIdx.x;

    // Broadcast scalars (L1/L2 broadcast; negligible)
    float fric = fabsf(params[0]);
    float damp = fabsf(params[1]);
    float R0 = expf(cp[0]);
    float R1 = expf(cp[1]);
    float R2 = expf(cp[2]);
    float Qd0 = expf(cp[3]);   // states 0,1
    float Qd2 = expf(cp[4]);   // states 2,3
    float Qd4 = expf(cp[5]);   // state 4
    float Qd5 = expf(cp[6]);   // state 5

    float loss = 0.0f;

    if (n < N) {
        // State
        float sx0 = init_state[n*6+0];
        float sx1 = init_state[n*6+1];
        float sx2 = init_state[n*6+2];
        float sx3 = init_state[n*6+3];
        float sx4 = init_state[n*6+4];
        float sx5 = init_state[n*6+5];

        // Symmetric covariance P = 0.01*I
        float p00=0.01f,p01=0.f,p02=0.f,p03=0.f,p04=0.f,p05=0.f;
        float p11=0.01f,p12=0.f,p13=0.f,p14=0.f,p15=0.f;
        float p22=0.01f,p23=0.f,p24=0.f,p25=0.f;
        float p33=0.01f,p34=0.f,p35=0.f;
        float p44=0.01f,p45=0.f;
        float p55=0.01f;

        const float* mp = meas + (size_t)n * T * 3;
        float z0 = mp[0], z1 = mp[1], z2 = mp[2];

        const float cF   = 1.0f - DT*damp;       // F[5,5]
        const float fgk  = fric * GRAV * KS;     // for Jacobian dv term
        const float fg   = fric * GRAV;
        const float DT2  = DT*DT;

        #pragma unroll 1
        for (int t = 0; t < T; t++) {
            // --- prefetch next measurement (hide L2 latency under compute) ---
            float nz0 = 0.f, nz1 = 0.f, nz2 = 0.f;
            if (t + 1 < T) {
                nz0 = mp[(t+1)*3 + 0];
                nz1 = mp[(t+1)*3 + 1];
                nz2 = mp[(t+1)*3 + 2];
            }

            // --- predict ---
            float th0 = tanhf(KS * sx2);
            float th1 = tanhf(KS * sx3);
            float xp0 = sx0 + DT * sx2;
            float xp1 = sx1 + DT * sx3;
            float xp2 = sx2 - DT * (damp * sx2 + fg * th0);
            float xp3 = sx3 - DT * (damp * sx3 + fg * th1);
            float xp4 = sx4 + DT * sx5;
            float xp5 = sx5 - DT * damp * sx5;

            // Jacobian diagonal terms
            float a = 1.0f - DT * (damp + fgk * (1.0f - th0*th0));
            float b = 1.0f - DT * (damp + fgk * (1.0f - th1*th1));
            float c = cF;

            // --- P_pred = F P F^T + Q (sparse F, symmetric P) ---
            float Pp00 = p00 + 2.f*DT*p02 + DT2*p22 + Qd0;
            float Pp01 = p01 + DT*p03 + DT*p12 + DT2*p23;
            float Pp02 = a * (p02 + DT*p22);
            float Pp03 = b * (p03 + DT*p23);
            float Pp04 = p04 + DT*p05 + DT*p24 + DT2*p25;
            float Pp05 = c * (p05 + DT*p25);
            float Pp11 = p11 + 2.f*DT*p13 + DT2*p33 + Qd0;
            float Pp12 = a * (p12 + DT*p23);
            float Pp13 = b * (p13 + DT*p33);
            float Pp14 = p14 + DT*p15 + DT*p34 + DT2*p35;
            float Pp15 = c * (p15 + DT*p35);
            float Pp22 = a*a*p22 + Qd2;
            float Pp23 = a*b*p23;
            float Pp24 = a * (p24 + DT*p25);
            float Pp25 = a*c*p25;
            float Pp33 = b*b*p33 + Qd2;
            float Pp34 = b * (p34 + DT*p35);
            float Pp35 = b*c*p35;
            float Pp44 = p44 + 2.f*DT*p45 + DT2*p55 + Qd4;
            float Pp45 = c * (p45 + DT*p55);
            float Pp55 = c*c*p55 + Qd5;

            // --- innovation (measured states 0,1,4) ---
            float y0 = z0 - xp0;
            float y1 = z1 - xp1;
            float y2 = z2 - xp4;
            if (y2 >  WRAP) y2 -= TWOPI;
            else if (y2 < -WRAP) y2 += TWOPI;

            // --- S = H Ppred H^T + R (3x3 symmetric) ---
            float s00 = Pp00 + R0;
            float s01 = Pp01;
            float s02 = Pp04;
            float s11 = Pp11 + R1;
            float s12 = Pp14;
            float s22 = Pp44 + R2;

            // adjugate inverse
            float c00 = s11*s22 - s12*s12;
            float c01 = s02*s12 - s01*s22;
            float c02 = s01*s12 - s02*s11;
            float det = s00*c00 + s01*c01 + s02*c02;
            float inv = 1.0f / det;
            float i00 = c00*inv;
            float i01 = c01*inv;
            float i02 = c02*inv;
            float i11 = (s00*s22 - s02*s02)*inv;
            float i12 = (s01*s02 - s00*s12)*inv;
            float i22 = (s00*s11 - s01*s01)*inv;

            float logdet = logf(det);

            // maha = y^T Sinv y
            float w0 = i00*y0 + i01*y1 + i02*y2;
            float w1 = i01*y0 + i11*y1 + i12*y2;
            float w2 = i02*y0 + i12*y1 + i22*y2;
            float maha = y0*w0 + y1*w1 + y2*w2;
            loss += 0.5f * (logdet + maha);

            // --- U = Ppred[:, midx] (columns 0,1,4 via symmetry) ---
            float u00=Pp00, u01v=Pp01, u02v=Pp04;
            float u10=Pp01, u11v=Pp11, u12v=Pp14;
            float u20=Pp02, u21v=Pp12, u22v=Pp24;
            float u30=Pp03, u31v=Pp13, u32v=Pp34;
            float u40=Pp04, u41v=Pp14, u42v=Pp44;
            float u50=Pp05, u51v=Pp15, u52v=Pp45;

            // --- K = U * Sinv (6x3) ---
            float k00 = u00*i00 + u01v*i01 + u02v*i02;
            float k01 = u00*i01 + u01v*i11 + u02v*i12;
            float k02 = u00*i02 + u01v*i12 + u02v*i22;
            float k10 = u10*i00 + u11v*i01 + u12v*i02;
            float k11 = u10*i01 + u11v*i11 + u12v*i12;
            float k12 = u10*i02 + u11v*i12 + u12v*i22;
            float k20 = u20*i00 + u21v*i01 + u22v*i02;
            float k21 = u20*i01 + u21v*i11 + u22v*i12;
            float k22 = u20*i02 + u21v*i12 + u22v*i22;
            float k30 = u30*i00 + u31v*i01 + u32v*i02;
            float k31 = u30*i01 + u31v*i11 + u32v*i12;
            float k32 = u30*i02 + u31v*i12 + u32v*i22;
            float k40 = u40*i00 + u41v*i01 + u42v*i02;
            float k41 = u40*i01 + u41v*i11 + u42v*i12;
            float k42 = u40*i02 + u41v*i12 + u42v*i22;
            float k50 = u50*i00 + u51v*i01 + u52v*i02;
            float k51 = u50*i01 + u51v*i11 + u52v*i12;
            float k52 = u50*i02 + u51v*i12 + u52v*i22;

            // --- state update ---
            sx0 = xp0 + k00*y0 + k01*y1 + k02*y2;
            sx1 = xp1 + k10*y0 + k11*y1 + k12*y2;
            sx2 = xp2 + k20*y0 + k21*y1 + k22*y2;
            sx3 = xp3 + k30*y0 + k31*y1 + k32*y2;
            sx4 = xp4 + k40*y0 + k41*y1 + k42*y2;
            sx5 = xp5 + k50*y0 + k51*y1 + k52*y2;

            // --- P_new[i][j] = Ppred[i][j] - sum_m K[i][m]*U[j][m]  (upper triangle) ---
            p00 = Pp00 - (k00*u00 + k01*u01v + k02*u02v);
            p01 = Pp01 - (k00*u10 + k01*u11v + k02*u12v);
            p02 = Pp02 - (k00*u20 + k01*u21v + k02*u22v);
            p03 = Pp03 - (k00*u30 + k01*u31v + k02*u32v);
            p04 = Pp04 - (k00*u40 + k01*u41v + k02*u42v);
            p05 = Pp05 - (k00*u50 + k01*u51v + k02*u52v);
            p11 = Pp11 - (k10*u10 + k11*u11v + k12*u12v);
            p12 = Pp12 - (k10*u20 + k11*u21v + k12*u22v);
            p13 = Pp13 - (k10*u30 + k11*u31v + k12*u32v);
            p14 = Pp14 - (k10*u40 + k11*u41v + k12*u42v);
            p15 = Pp15 - (k10*u50 + k11*u51v + k12*u52v);
            p22 = Pp22 - (k20*u20 + k21*u21v + k22*u22v);
            p23 = Pp23 - (k20*u30 + k21*u31v + k22*u32v);
            p24 = Pp24 - (k20*u40 + k21*u41v + k22*u42v);
            p25 = Pp25 - (k20*u50 + k21*u51v + k22*u52v);
            p33 = Pp33 - (k30*u30 + k31*u31v + k32*u32v);
            p34 = Pp34 - (k30*u40 + k31*u41v + k32*u42v);
            p35 = Pp35 - (k30*u50 + k31*u51v + k32*u52v);
            p44 = Pp44 - (k40*u40 + k41*u41v + k42*u42v);
            p45 = Pp45 - (k40*u50 + k41*u51v + k42*u52v);
            p55 = Pp55 - (k50*u50 + k51*u51v + k52*u52v);

            z0 = nz0; z1 = nz1; z2 = nz2;
        }
    }

    // Deterministic block reduction
    __shared__ float red[THREADS];
    red[threadIdx.x] = loss;
    __syncthreads();
    #pragma unroll
    for (int st = THREADS/2; st > 0; st >>= 1) {
        if (threadIdx.x < st) red[threadIdx.x] += red[threadIdx.x + st];
        __syncthreads();
    }
    if (threadIdx.x == 0) g_partials[blockIdx.x] = red[0];
}

__global__ void reduce_kernel(float* __restrict__ out, int nblocks, int N)
{
    __shared__ float s[256];
    int i = threadIdx.x;
    float v = 0.0f;
    for (int j = i; j < nblocks; j += 256) v += g_partials[j];
    s[i] = v;
    __syncthreads();
    #pragma unroll
    for (int st = 128; st > 0; st >>= 1) {
        if (i < st) s[i] += s[i + st];
        __syncthreads();
    }
    if (i == 0) out[0] = s[0] / (float)N;
}

extern "C" void kernel_launch(void* const* d_in, const int* in_sizes, int n_in,
                              void* d_out, int out_size)
{
    const float* params = (const float*)d_in[0];
    const float* cp     = (const float*)d_in[1];
    const float* x0     = (const float*)d_in[2];
    const float* meas   = (const float*)d_in[3];
    float* out = (float*)d_out;

    int N = in_sizes[2] / 6;
    int T = in_sizes[3] / (N * 3);
    int nblocks = (N + THREADS - 1) / THREADS;

    ekf_kernel<<<nblocks, THREADS>>>(params, cp, x0, meas, N, T);
    reduce_kernel<<<1, 256>>>(out, nblocks, N);
}

// round 2
// speedup vs baseline: 1.7819x; 1.7819x over previous
#include <cuda_runtime.h>
#include <math.h>

// Batched EKF, decomposed: the 6x6 filter factors exactly into three
// independent 2x2 Kalman filters (P0,Q,R diagonal; F block-diagonal over
// {0,2},{1,3},{4,5}; H measures one state per block => S diagonal).
// One thread per segment; all state in registers; fused deterministic
// grid reduction (last-block pattern).

#define THREADS 32

__device__ float g_partials[512];
__device__ int   g_count = 0;

__device__ __forceinline__ float tanh_fast(float x){ float y; asm("tanh.approx.f32 %0, %1;" : "=f"(y) : "f"(x)); return y; }
__device__ __forceinline__ float rcp_fast (float x){ float y; asm("rcp.approx.f32 %0, %1;"  : "=f"(y) : "f"(x)); return y; }
__device__ __forceinline__ float lg2_fast (float x){ float y; asm("lg2.approx.f32 %0, %1;"  : "=f"(y) : "f"(x)); return y; }

__global__ void __launch_bounds__(THREADS) ekf_kernel(
    const float* __restrict__ params,
    const float* __restrict__ cp,
    const float* __restrict__ init_state,
    const float* __restrict__ meas,
    float* __restrict__ out,
    int N, int T)
{
    const float DT    = 1.0f / 120.0f;
    const float GRAV  = 9.81f;
    const float KS    = 100.0f;
    const float WRAP  = 4.71238898038469f;   // 1.5*pi
    const float TWOPI = 6.283185307179586f;
    const float LN2   = 0.6931471805599453f;

    const float fric = fabsf(params[0]);
    const float damp = fabsf(params[1]);
    const float R0 = expf(cp[0]);
    const float R1 = expf(cp[1]);
    const float R2 = expf(cp[2]);
    const float Qp = expf(cp[3]);   // pos states 0,1
    const float Qv = expf(cp[4]);   // vel states 2,3
    const float Qt = expf(cp[5]);   // theta 4
    const float Qo = expf(cp[6]);   // omega 5

    const float fg    = fric * GRAV;
    const float cF    = 1.0f - DT * damp;         // linear vel decay / F[5,5]
    const float DTfgk = DT * fg * KS;             // a = cF - DTfgk*(1-t^2)
    const float cF2   = cF * cF;

    int n = blockIdx.x * THREADS + threadIdx.x;

    float acc_l2 = 0.0f;   // sum of lg2(det S_t)
    float acc_m  = 0.0f;   // sum of mahalanobis terms

    if (n < N) {
        float xA = init_state[n*6+0], vA = init_state[n*6+2];   // block {0,2}, meas z0
        float xB = init_state[n*6+1], vB = init_state[n*6+3];   // block {1,3}, meas z1
        float xC = init_state[n*6+4], vC = init_state[n*6+5];   // block {4,5}, meas z2 (wrap)

        float pA00=0.01f, pA01=0.0f, pA11=0.01f;
        float pB00=0.01f, pB01=0.0f, pB11=0.01f;
        float pC00=0.01f, pC01=0.0f, pC11=0.01f;

        const float*  mp  = meas + (size_t)n * T * 3;
        const float4* mp4 = (const float4*)mp;

#define STEP(z0_, z1_, z2_) do {                                              \
        /* block A (nonlinear) */                                             \
        float tA   = tanh_fast(KS * vA);                                      \
        float xpA  = fmaf(DT, vA, xA);                                        \
        float vpA  = fmaf(-DT, fmaf(fg, tA, damp * vA), vA);                  \
        float aA   = fmaf(-DTfgk, fmaf(-tA, tA, 1.0f), cF);                   \
        float PpA00 = fmaf(DT, fmaf(DT, pA11, pA01 + pA01), pA00) + Qp;       \
        float PpA01 = aA * fmaf(DT, pA11, pA01);                              \
        float PpA11 = fmaf(aA * aA, pA11, Qv);                                \
        float yA = (z0_) - xpA;                                               \
        float sA = PpA00 + R0;                                                \
        float iA = rcp_fast(sA);                                              \
        float k0A = PpA00 * iA, k1A = PpA01 * iA;                             \
        xA = fmaf(k0A, yA, xpA);  vA = fmaf(k1A, yA, vpA);                    \
        float omA = 1.0f - k0A;                                               \
        pA00 = PpA00 * omA; pA01 = PpA01 * omA;                               \
        pA11 = fmaf(-k1A, PpA01, PpA11);                                      \
        acc_m = fmaf(yA * yA, iA, acc_m);                                     \
        /* block B (nonlinear) */                                             \
        float tB   = tanh_fast(KS * vB);                                      \
        float xpB  = fmaf(DT, vB, xB);                                        \
        float vpB  = fmaf(-DT, fmaf(fg, tB, damp * vB), vB);                  \
        float aB   = fmaf(-DTfgk, fmaf(-tB, tB, 1.0f), cF);                   \
        float PpB00 = fmaf(DT, fmaf(DT, pB11, pB01 + pB01), pB00) + Qp;       \
        float PpB01 = aB * fmaf(DT, pB11, pB01);                              \
        float PpB11 = fmaf(aB * aB, pB11, Qv);                                \
        float yB = (z1_) - xpB;                                               \
        float sB = PpB00 + R1;                                                \
        float iB = rcp_fast(sB);                                              \
        float k0B = PpB00 * iB, k1B = PpB01 * iB;                             \
        xB = fmaf(k0B, yB, xpB);  vB = fmaf(k1B, yB, vpB);                    \
        float omB = 1.0f - k0B;                                               \
        pB00 = PpB00 * omB; pB01 = PpB01 * omB;                               \
        pB11 = fmaf(-k1B, PpB01, PpB11);                                      \
        acc_m = fmaf(yB * yB, iB, acc_m);                                     \
        /* block C (linear, angle wrap) */                                    \
        float xpC  = fmaf(DT, vC, xC);                                        \
        float vpC  = cF * vC;                                                 \
        float PpC00 = fmaf(DT, fmaf(DT, pC11, pC01 + pC01), pC00) + Qt;       \
        float PpC01 = cF * fmaf(DT, pC11, pC01);                              \
        float PpC11 = fmaf(cF2, pC11, Qo);                                    \
        float yC = (z2_) - xpC;                                               \
        if      (yC >  WRAP) yC -= TWOPI;                                     \
        else if (yC < -WRAP) yC += TWOPI;                                     \
        float sC = PpC00 + R2;                                                \
        float iC = rcp_fast(sC);                                              \
        float k0C = PpC00 * iC, k1C = PpC01 * iC;                             \
        xC = fmaf(k0C, yC, xpC);  vC = fmaf(k1C, yC, vpC);                    \
        float omC = 1.0f - k0C;                                               \
        pC00 = PpC00 * omC; pC01 = PpC01 * omC;                               \
        pC11 = fmaf(-k1C, PpC01, PpC11);                                      \
        acc_m = fmaf(yC * yC, iC, acc_m);                                     \
        /* one log for all three blocks: log det S = log(sA*sB*sC) */         \
        acc_l2 += lg2_fast(sA * sB * sC);                                     \
    } while (0)

        int G = T >> 2;   // groups of 4 timesteps = 3 float4s
        if ((T & 3) == 0) {
            float4 c0 = mp4[0], c1 = mp4[1], c2 = mp4[2];
            for (int g = 0; g < G; g++) {
                float4 n0, n1, n2;
                if (g + 1 < G) {
                    int b = (g + 1) * 3;
                    n0 = mp4[b]; n1 = mp4[b+1]; n2 = mp4[b+2];
                }
                STEP(c0.x, c0.y, c0.z);
                STEP(c0.w, c1.x, c1.y);
                STEP(c1.z, c1.w, c2.x);
                STEP(c2.y, c2.z, c2.w);
                c0 = n0; c1 = n1; c2 = n2;
            }
        } else {
            for (int t = 0; t < T; t++) {
                float z0 = mp[t*3+0], z1 = mp[t*3+1], z2 = mp[t*3+2];
                STEP(z0, z1, z2);
            }
        }
#undef STEP
    }

    float loss = 0.5f * fmaf(LN2, acc_l2, acc_m);

    // warp reduction (deterministic fixed tree)
    #pragma unroll
    for (int o = 16; o > 0; o >>= 1)
        loss += __shfl_down_sync(0xffffffffu, loss, o);

    int nb = gridDim.x;
    int last = 0;
    if (threadIdx.x == 0) {
        g_partials[blockIdx.x] = loss;
        __threadfence();
        int old = atomicAdd(&g_count, 1);
        last = (old == nb - 1);
    }
    last = __shfl_sync(0xffffffffu, last, 0);
    if (last) {
        __threadfence();
        float s = 0.0f;
        for (int j = (int)threadIdx.x; j < nb; j += 32)
            s += g_partials[j];
        #pragma unroll
        for (int o = 16; o > 0; o >>= 1)
            s += __shfl_down_sync(0xffffffffu, s, o);
        if (threadIdx.x == 0) {
            out[0] = s / (float)N;
            g_count = 0;   // reset for next graph replay
        }
    }
}

extern "C" void kernel_launch(void* const* d_in, const int* in_sizes, int n_in,
                              void* d_out, int out_size)
{
    const float* params = (const float*)d_in[0];
    const float* cp     = (const float*)d_in[1];
    const float* x0     = (const float*)d_in[2];
    const float* meas   = (const float*)d_in[3];
    float* out = (float*)d_out;

    int N = in_sizes[2] / 6;
    int T = in_sizes[3] / (N * 3);
    int nblocks = (N + THREADS - 1) / THREADS;

    ekf_kernel<<<nblocks, THREADS>>>(params, cp, x0, meas, out, N, T);
}